// round 7
// baseline (speedup 1.0000x reference)
#include <cuda_runtime.h>
#include <cuda_bf16.h>
#include <math.h>

// ---- static problem config (matches reference) ----
#define N_ATOMS 16384
#define NUM_BATCH 32
#define ATOMS_PER_BATCH 512
#define N_PAIRS 1048576

#define ALPHA_F       0.401f            // 4/10 + 0.001
#define K2FAC_F       1.5547167f        // 0.25 / ALPHA^2
#define TWO_PI_F      6.283185307179586f
#define ONE_OVER_SQRTPI_F 0.5641895835477563f
#define EPS_F         1e-8f
#define FULL 0xFFFFFFFFu

#define REAL_BLOCKS 128                 // 128 blocks * 8 warps * 1024 pairs = 1M
#define PAIRS_PER_WARP 1024
#define KMAXI 8

// canonical-half k list passed as kernel parameter (constant bank)
#define KPAD_MAX 1120                   // 35 blocks of 32 k-vectors, 17.9KB
struct KList {
    float4 k[KPAD_MAX];                 // (mx, my, mz, weight) weight=2 real, 0 pad
};

// scratch (no allocations; device globals start zeroed, and k_final
// restores them to zero each call so graph replays are deterministic)
__device__ float g_recip[NUM_BATCH];
__device__ float g_ereal[N_ATOMS];

// ------------------------------------------------------------------
// fused main: real-space blocks interleaved (1-in-S) with recip blocks.
// recip block: one batch b, 32 k-vectors (8 warps x 4 k). Stages the
// batch's 512 atoms as (theta_xyz, q) float4 in SMEM, computed on the
// fly from R and cell. Each lane loads an atom once and feeds 4 dots +
// 4 __sincosf pairs (LDS amortized 4x). Shuffle-reduce 4 structure
// factors, fold weight*qg*|S|^2 into a block scalar, one atomic per
// block into g_recip[b].
// real block: coalesced pairs, warp segmented scan over sorted idx_i,
// atomics into g_ereal.
// ------------------------------------------------------------------
__global__ void __launch_bounds__(256) k_main(
        const __grid_constant__ KList kl,
        const float* __restrict__ Qa,
        const float* __restrict__ rij,
        const int*   __restrict__ idx_i,
        const int*   __restrict__ idx_j,
        const float* __restrict__ R,
        const float* __restrict__ cell,
        int S) {
    int bid = blockIdx.x;
    int warp = threadIdx.x >> 5;
    int lane = threadIdx.x & 31;

    int g = bid / S;
    int r = bid - g * S;
    bool isReal = (r == 0) && (g < REAL_BLOCKS);

    if (isReal) {
        // ---------------- real space ----------------
        int gw = g * 8 + warp;
        int base = gw * PAIRS_PER_WARP;
#pragma unroll 2
        for (int it = 0; it < PAIRS_PER_WARP / 32; it++) {
            int p = base + it * 32 + lane;          // coalesced
            int ii = idx_i[p];
            int jj = idx_j[p];
            float rr = rij[p];
            float fac = __ldg(&Qa[ii]) * __ldg(&Qa[jj]);

            // C-inf switch, fast path
            float x = (rr - 2.5f) * 0.2f;
            float f;
            if (x <= 0.0f)      f = 1.0f;
            else if (x >= 1.0f) f = 0.0f;
            else {
                float fp = __expf(-__frcp_rn(x));
                float fm = __expf(-__frcp_rn(1.0f - x));
                f = fm * __frcp_rn(fp + fm);
            }
            float damped = rsqrtf(fmaf(rr, rr, 1.0f));
            float coul = __frcp_rn(rr);

            // erfc via Abramowitz-Stegun 7.1.26 (abs err <= 1.5e-7)
            float xa = ALPHA_F * rr;
            float t = __frcp_rn(fmaf(0.3275911f, xa, 1.0f));
            float poly = t * fmaf(t, fmaf(t, fmaf(t, fmaf(t, 1.061405429f,
                                -1.453152027f), 1.421413741f),
                                -0.284496736f), 0.254829592f);
            float er = poly * __expf(-xa * xa);

            float pw = fac * (f * damped + (1.0f - f) * coul) * er;

            // warp segmented reduction over sorted ii
            int prev = __shfl_up_sync(FULL, ii, 1);
            bool head = (lane == 0) || (ii != prev);
            unsigned hm = __ballot_sync(FULL, head);
            unsigned below = hm & (0xFFFFFFFFu >> (31 - lane));
            int hp = 31 - __clz(below);
            float s = pw;
#pragma unroll
            for (int d = 1; d < 32; d <<= 1) {
                float v = __shfl_up_sync(FULL, s, d);
                if (lane >= hp + d) s += v;
            }
            bool lastv = (lane == 31) || ((hm >> (lane + 1)) & 1u);
            if (lastv) atomicAdd(&g_ereal[ii], s);
        }
    } else {
        // ---------------- reciprocal space ----------------
        int nRealBefore = g + (r > 0 ? 1 : 0);
        if (nRealBefore > REAL_BLOCKS) nRealBefore = REAL_BLOCKS;
        int recipIdx = bid - nRealBefore;
        int b = recipIdx & (NUM_BATCH - 1);     // consecutive blocks -> different batches
        int kblk = recipIdx >> 5;

        __shared__ float4 s4[ATOMS_PER_BATCH];  // (theta_x, theta_y, theta_z, q)
        __shared__ float sacc;

        float ax = TWO_PI_F * __frcp_rn(cell[b * 9 + 0]);
        float ay = TWO_PI_F * __frcp_rn(cell[b * 9 + 4]);
        float az = TWO_PI_F * __frcp_rn(cell[b * 9 + 8]);

        if (threadIdx.x == 0) sacc = 0.0f;
        for (int a = threadIdx.x; a < ATOMS_PER_BATCH; a += 256) {
            int n = b * ATOMS_PER_BATCH + a;
            float4 v;
            v.x = R[n * 3 + 0] * ax;
            v.y = R[n * 3 + 1] * ay;
            v.z = R[n * 3 + 2] * az;
            v.w = Qa[n];
            s4[a] = v;
        }
        __syncthreads();

        int kk = kblk * 32 + warp * 4;          // 4 k-vectors per warp
        float4 k0 = kl.k[kk + 0];
        float4 k1 = kl.k[kk + 1];
        float4 k2v = kl.k[kk + 2];
        float4 k3 = kl.k[kk + 3];

        float cr0 = 0.f, ci0 = 0.f, cr1 = 0.f, ci1 = 0.f;
        float cr2 = 0.f, ci2 = 0.f, cr3 = 0.f, ci3 = 0.f;

#pragma unroll 2
        for (int a = lane; a < ATOMS_PER_BATCH; a += 32) {
            float4 v = s4[a];
            float q = v.w;
            float d0 = fmaf(k0.x, v.x, fmaf(k0.y, v.y, k0.z * v.z));
            float d1 = fmaf(k1.x, v.x, fmaf(k1.y, v.y, k1.z * v.z));
            float d2 = fmaf(k2v.x, v.x, fmaf(k2v.y, v.y, k2v.z * v.z));
            float d3 = fmaf(k3.x, v.x, fmaf(k3.y, v.y, k3.z * v.z));
            float s0, c0, s1, c1, s2, c2, s3, c3;
            __sincosf(d0, &s0, &c0);
            __sincosf(d1, &s1, &c1);
            __sincosf(d2, &s2, &c2);
            __sincosf(d3, &s3, &c3);
            cr0 = fmaf(q, c0, cr0); ci0 = fmaf(q, s0, ci0);
            cr1 = fmaf(q, c1, cr1); ci1 = fmaf(q, s1, ci1);
            cr2 = fmaf(q, c2, cr2); ci2 = fmaf(q, s2, ci2);
            cr3 = fmaf(q, c3, cr3); ci3 = fmaf(q, s3, ci3);
        }
#pragma unroll
        for (int o = 16; o > 0; o >>= 1) {
            cr0 += __shfl_down_sync(FULL, cr0, o);
            ci0 += __shfl_down_sync(FULL, ci0, o);
            cr1 += __shfl_down_sync(FULL, cr1, o);
            ci1 += __shfl_down_sync(FULL, ci1, o);
            cr2 += __shfl_down_sync(FULL, cr2, o);
            ci2 += __shfl_down_sync(FULL, ci2, o);
            cr3 += __shfl_down_sync(FULL, cr3, o);
            ci3 += __shfl_down_sync(FULL, ci3, o);
        }
        if (lane == 0) {
            float kx, ky, kz, kk2, qg, acc = 0.0f;
            kx = k0.x * ax; ky = k0.y * ay; kz = k0.z * az;
            kk2 = kx * kx + ky * ky + kz * kz;
            qg = __expf(-K2FAC_F * kk2) * __frcp_rn(kk2);
            acc = fmaf(k0.w * qg, fmaf(cr0, cr0, ci0 * ci0), acc);
            kx = k1.x * ax; ky = k1.y * ay; kz = k1.z * az;
            kk2 = kx * kx + ky * ky + kz * kz;
            qg = __expf(-K2FAC_F * kk2) * __frcp_rn(kk2);
            acc = fmaf(k1.w * qg, fmaf(cr1, cr1, ci1 * ci1), acc);
            kx = k2v.x * ax; ky = k2v.y * ay; kz = k2v.z * az;
            kk2 = kx * kx + ky * ky + kz * kz;
            qg = __expf(-K2FAC_F * kk2) * __frcp_rn(kk2);
            acc = fmaf(k2v.w * qg, fmaf(cr2, cr2, ci2 * ci2), acc);
            kx = k3.x * ax; ky = k3.y * ay; kz = k3.z * az;
            kk2 = kx * kx + ky * ky + kz * kz;
            qg = __expf(-K2FAC_F * kk2) * __frcp_rn(kk2);
            acc = fmaf(k3.w * qg, fmaf(cr3, cr3, ci3 * ci3), acc);
            atomicAdd(&sacc, acc);
        }
        __syncthreads();
        if (threadIdx.x == 0 && sacc != 0.0f) atomicAdd(&g_recip[b], sacc);
    }
}

// ------------------------------------------------------------------
// finalize: one block per batch, 512 threads. Block-reduce wnorm,
// combine e_real + w*e_recip - e_self, and RESET scratch to zero so
// the next graph replay starts from a clean state.
// ------------------------------------------------------------------
__global__ void k_final(const float* __restrict__ Qa,
                        const float* __restrict__ cell,
                        float* __restrict__ out) {
    int b = blockIdx.x;
    int a = threadIdx.x;            // 0..511
    int n = b * ATOMS_PER_BATCH + a;
    __shared__ float s[512];

    float q = Qa[n];
    float q2 = q * q;
    float w = q2 + EPS_F;

    float er = g_ereal[n];
    g_ereal[n] = 0.0f;              // restore invariant for next replay
    float rec = g_recip[b];

    s[a] = w;
    __syncthreads();
    for (int st = 256; st > 0; st >>= 1) {
        if (a < st) s[a] += s[a + st];
        __syncthreads();
    }
    float wnorm = s[0];
    if (a == 0) g_recip[b] = 0.0f;  // after all threads read rec (pre-reduce)

    float Lx = cell[b * 9 + 0];
    float Ly = cell[b * 9 + 4];
    float Lz = cell[b * 9 + 8];
    float erec = (w / wnorm) * (TWO_PI_F / (Lx * Ly * Lz)) * rec;
    out[n] = er + erec - ALPHA_F * ONE_OVER_SQRTPI_F * q2;
}

// ------------------------------------------------------------------
extern "C" void kernel_launch(void* const* d_in, const int* in_sizes, int n_in,
                              void* d_out, int out_size) {
    const float* Qa    = (const float*)d_in[0];
    const float* rij   = (const float*)d_in[1];
    const float* R     = (const float*)d_in[2];
    const float* cell  = (const float*)d_in[3];
    const int*   idx_i = (const int*)d_in[5];
    const int*   idx_j = (const int*)d_in[6];
    float* out = (float*)d_out;

    // Build canonical half of the k lattice on the host (deterministic:
    // integer vectors with 0 < |k|^2 <= KMAX^2; keep k > 0 lexicographically).
    static KList h_kl;
    int nk = 0;
    for (int mx = -KMAXI; mx <= KMAXI; mx++)
        for (int my = -KMAXI; my <= KMAXI; my++)
            for (int mz = -KMAXI; mz <= KMAXI; mz++) {
                int k2 = mx * mx + my * my + mz * mz;
                if (k2 == 0 || k2 > KMAXI * KMAXI) continue;
                bool canon = (mx > 0) || (mx == 0 && (my > 0 || (my == 0 && mz > 0)));
                if (!canon) continue;
                if (nk < KPAD_MAX) {
                    h_kl.k[nk].x = (float)mx;
                    h_kl.k[nk].y = (float)my;
                    h_kl.k[nk].z = (float)mz;
                    h_kl.k[nk].w = 2.0f;     // +k and -k
                    nk++;
                }
            }
    int KB = (nk + 31) / 32;                 // 32 k-vectors per block
    for (int i = nk; i < KB * 32; i++)       // harmless padding
        h_kl.k[i] = make_float4(1.0f, 0.0f, 0.0f, 0.0f);

    int recip_blocks = KB * NUM_BATCH;
    int total = recip_blocks + REAL_BLOCKS;
    int S = total / REAL_BLOCKS;             // interleave stride (>=1)
    if (S < 1) S = 1;

    k_main<<<total, 256>>>(h_kl, Qa, rij, idx_i, idx_j, R, cell, S);
    k_final<<<NUM_BATCH, ATOMS_PER_BATCH>>>(Qa, cell, out);
}

// round 8
// speedup vs baseline: 1.6941x; 1.6941x over previous
#include <cuda_runtime.h>
#include <cuda_bf16.h>
#include <math.h>

// ---- static problem config (matches reference) ----
#define N_ATOMS 16384
#define NUM_BATCH 32
#define ATOMS_PER_BATCH 512
#define N_PAIRS 1048576

#define ALPHA_F       0.401f            // 4/10 + 0.001
#define K2FAC_F       1.5547167f        // 0.25 / ALPHA^2
#define TWO_PI_F      6.283185307179586f
#define ONE_OVER_SQRTPI_F 0.5641895835477563f
#define EPS_F         1e-8f
#define FULL 0xFFFFFFFFu

#define REAL_BLOCKS 128                 // 128 blocks * 8 warps * 1024 pairs = 1M
#define PAIRS_PER_WARP 1024
#define KMAXI 8

// ------------------------------------------------------------------
// Compile-time canonical half of the k lattice (KMAX=8 is static).
// canonical: mx>0 | (mx=0 & my>0) | (mx=0 & my=0 & mz>0); 0<|k|^2<=64.
// Stored in __constant__ memory -> uniform LDC, zero runtime setup.
// ------------------------------------------------------------------
struct alignas(16) KEntry { float x, y, z, w; };

constexpr int count_khalf() {
    int n = 0;
    for (int mx = -KMAXI; mx <= KMAXI; mx++)
        for (int my = -KMAXI; my <= KMAXI; my++)
            for (int mz = -KMAXI; mz <= KMAXI; mz++) {
                int k2 = mx * mx + my * my + mz * mz;
                if (k2 == 0 || k2 > KMAXI * KMAXI) continue;
                if ((mx > 0) || (mx == 0 && (my > 0 || (my == 0 && mz > 0)))) n++;
            }
    return n;
}
constexpr int NK   = count_khalf();
constexpr int KB   = (NK + 31) / 32;     // 32 k-vectors per recip block
constexpr int KPAD = KB * 32;

struct KTable { KEntry e[KPAD]; };

constexpr KTable make_ktable() {
    KTable t{};
    int n = 0;
    for (int mx = -KMAXI; mx <= KMAXI; mx++)
        for (int my = -KMAXI; my <= KMAXI; my++)
            for (int mz = -KMAXI; mz <= KMAXI; mz++) {
                int k2 = mx * mx + my * my + mz * mz;
                if (k2 == 0 || k2 > KMAXI * KMAXI) continue;
                if (!((mx > 0) || (mx == 0 && (my > 0 || (my == 0 && mz > 0))))) continue;
                t.e[n].x = (float)mx; t.e[n].y = (float)my;
                t.e[n].z = (float)mz; t.e[n].w = 2.0f;    // +k and -k
                n++;
            }
    for (; n < KPAD; n++) { t.e[n].x = 1.0f; t.e[n].y = 0.0f; t.e[n].z = 0.0f; t.e[n].w = 0.0f; }
    return t;
}
constexpr KTable h_ktable = make_ktable();
__constant__ KTable c_kt = h_ktable;

#define WNORM_BLOCKS 32
#define RECIP_BASE   (REAL_BLOCKS + WNORM_BLOCKS)
#define TOTAL_BLOCKS (RECIP_BASE + KB * NUM_BATCH)

// scratch (no allocations). g_recip_part / g_wnorm are overwritten every
// call (no reset needed); g_ereal is reset by its reader in k_final so
// every graph replay starts from zero.
__device__ float g_recip_part[KB * NUM_BATCH];
__device__ float g_wnorm[NUM_BATCH];
__device__ float g_ereal[N_ATOMS];

// ------------------------------------------------------------------
// fused main:
//   blocks [0, 128)           real space (coalesced pairs, warp segscan)
//   blocks [128, 160)         per-batch wnorm (overwrite g_wnorm)
//   blocks [160, 160+KB*32)   recip: one (batch, kblk); 8 warps x 4 k.
//     Stage 512 atoms as (theta_xyz, q) float4 in SMEM (theta computed
//     on the fly). Each staged atom feeds 4 dots + 4 __sincosf pairs.
//     Per-k shuffle reduce, fold w*qg*|S|^2, store partial (no atomics).
// ------------------------------------------------------------------
__global__ void __launch_bounds__(256) k_main(
        const float* __restrict__ Qa,
        const float* __restrict__ rij,
        const int*   __restrict__ idx_i,
        const int*   __restrict__ idx_j,
        const float* __restrict__ R,
        const float* __restrict__ cell) {
    int bid = blockIdx.x;
    int warp = threadIdx.x >> 5;
    int lane = threadIdx.x & 31;

    if (bid < REAL_BLOCKS) {
        // ---------------- real space ----------------
        int gw = bid * 8 + warp;
        int base = gw * PAIRS_PER_WARP;
#pragma unroll 2
        for (int it = 0; it < PAIRS_PER_WARP / 32; it++) {
            int p = base + it * 32 + lane;          // coalesced
            int ii = idx_i[p];
            int jj = idx_j[p];
            float rr = rij[p];
            float fac = __ldg(&Qa[ii]) * __ldg(&Qa[jj]);

            // C-inf switch, fast path
            float x = (rr - 2.5f) * 0.2f;
            float f;
            if (x <= 0.0f)      f = 1.0f;
            else if (x >= 1.0f) f = 0.0f;
            else {
                float fp = __expf(-__frcp_rn(x));
                float fm = __expf(-__frcp_rn(1.0f - x));
                f = fm * __frcp_rn(fp + fm);
            }
            float damped = rsqrtf(fmaf(rr, rr, 1.0f));
            float coul = __frcp_rn(rr);

            // erfc via Abramowitz-Stegun 7.1.26 (abs err <= 1.5e-7)
            float xa = ALPHA_F * rr;
            float t = __frcp_rn(fmaf(0.3275911f, xa, 1.0f));
            float poly = t * fmaf(t, fmaf(t, fmaf(t, fmaf(t, 1.061405429f,
                                -1.453152027f), 1.421413741f),
                                -0.284496736f), 0.254829592f);
            float er = poly * __expf(-xa * xa);

            float pw = fac * (f * damped + (1.0f - f) * coul) * er;

            // warp segmented reduction over sorted ii
            int prev = __shfl_up_sync(FULL, ii, 1);
            bool head = (lane == 0) || (ii != prev);
            unsigned hm = __ballot_sync(FULL, head);
            unsigned below = hm & (0xFFFFFFFFu >> (31 - lane));
            int hp = 31 - __clz(below);
            float s = pw;
#pragma unroll
            for (int d = 1; d < 32; d <<= 1) {
                float v = __shfl_up_sync(FULL, s, d);
                if (lane >= hp + d) s += v;
            }
            bool lastv = (lane == 31) || ((hm >> (lane + 1)) & 1u);
            if (lastv) atomicAdd(&g_ereal[ii], s);
        }
    } else if (bid < RECIP_BASE) {
        // ---------------- per-batch wnorm (overwrite) ----------------
        int b = bid - REAL_BLOCKS;
        __shared__ float sw[8];
        float acc = 0.0f;
        for (int a = threadIdx.x; a < ATOMS_PER_BATCH; a += 256) {
            float q = Qa[b * ATOMS_PER_BATCH + a];
            acc = fmaf(q, q, acc + EPS_F);
        }
#pragma unroll
        for (int o = 16; o > 0; o >>= 1) acc += __shfl_down_sync(FULL, acc, o);
        if (lane == 0) sw[warp] = acc;
        __syncthreads();
        if (threadIdx.x == 0) {
            float tot = 0.0f;
#pragma unroll
            for (int w2 = 0; w2 < 8; w2++) tot += sw[w2];
            g_wnorm[b] = tot;
        }
    } else {
        // ---------------- reciprocal space ----------------
        int idx = bid - RECIP_BASE;
        int b = idx & (NUM_BATCH - 1);          // consecutive blocks -> different batches
        int kblk = idx >> 5;

        __shared__ float4 s4[ATOMS_PER_BATCH];  // (theta_x, theta_y, theta_z, q)
        __shared__ float sacc[8];

        float ax = TWO_PI_F * __frcp_rn(cell[b * 9 + 0]);
        float ay = TWO_PI_F * __frcp_rn(cell[b * 9 + 4]);
        float az = TWO_PI_F * __frcp_rn(cell[b * 9 + 8]);

        for (int a = threadIdx.x; a < ATOMS_PER_BATCH; a += 256) {
            int n = b * ATOMS_PER_BATCH + a;
            float4 v;
            v.x = R[n * 3 + 0] * ax;
            v.y = R[n * 3 + 1] * ay;
            v.z = R[n * 3 + 2] * az;
            v.w = Qa[n];
            s4[a] = v;
        }
        __syncthreads();

        const float4* kt = reinterpret_cast<const float4*>(c_kt.e);
        int kk = kblk * 32 + warp * 4;          // 4 k-vectors per warp
        float4 k0 = kt[kk + 0];
        float4 k1 = kt[kk + 1];
        float4 k2v = kt[kk + 2];
        float4 k3 = kt[kk + 3];

        float cr0 = 0.f, ci0 = 0.f, cr1 = 0.f, ci1 = 0.f;
        float cr2 = 0.f, ci2 = 0.f, cr3 = 0.f, ci3 = 0.f;

#pragma unroll 4
        for (int a = lane; a < ATOMS_PER_BATCH; a += 32) {
            float4 v = s4[a];
            float q = v.w;
            float d0 = fmaf(k0.x, v.x, fmaf(k0.y, v.y, k0.z * v.z));
            float d1 = fmaf(k1.x, v.x, fmaf(k1.y, v.y, k1.z * v.z));
            float d2 = fmaf(k2v.x, v.x, fmaf(k2v.y, v.y, k2v.z * v.z));
            float d3 = fmaf(k3.x, v.x, fmaf(k3.y, v.y, k3.z * v.z));
            float s0, c0, s1, c1, s2, c2, s3, c3;
            __sincosf(d0, &s0, &c0);
            __sincosf(d1, &s1, &c1);
            __sincosf(d2, &s2, &c2);
            __sincosf(d3, &s3, &c3);
            cr0 = fmaf(q, c0, cr0); ci0 = fmaf(q, s0, ci0);
            cr1 = fmaf(q, c1, cr1); ci1 = fmaf(q, s1, ci1);
            cr2 = fmaf(q, c2, cr2); ci2 = fmaf(q, s2, ci2);
            cr3 = fmaf(q, c3, cr3); ci3 = fmaf(q, s3, ci3);
        }
#pragma unroll
        for (int o = 16; o > 0; o >>= 1) {
            cr0 += __shfl_down_sync(FULL, cr0, o);
            ci0 += __shfl_down_sync(FULL, ci0, o);
            cr1 += __shfl_down_sync(FULL, cr1, o);
            ci1 += __shfl_down_sync(FULL, ci1, o);
            cr2 += __shfl_down_sync(FULL, cr2, o);
            ci2 += __shfl_down_sync(FULL, ci2, o);
            cr3 += __shfl_down_sync(FULL, cr3, o);
            ci3 += __shfl_down_sync(FULL, ci3, o);
        }
        if (lane == 0) {
            float kx, ky, kz, kk2, qg, acc = 0.0f;
            kx = k0.x * ax; ky = k0.y * ay; kz = k0.z * az;
            kk2 = kx * kx + ky * ky + kz * kz;
            qg = __expf(-K2FAC_F * kk2) * __frcp_rn(kk2);
            acc = fmaf(k0.w * qg, fmaf(cr0, cr0, ci0 * ci0), acc);
            kx = k1.x * ax; ky = k1.y * ay; kz = k1.z * az;
            kk2 = kx * kx + ky * ky + kz * kz;
            qg = __expf(-K2FAC_F * kk2) * __frcp_rn(kk2);
            acc = fmaf(k1.w * qg, fmaf(cr1, cr1, ci1 * ci1), acc);
            kx = k2v.x * ax; ky = k2v.y * ay; kz = k2v.z * az;
            kk2 = kx * kx + ky * ky + kz * kz;
            qg = __expf(-K2FAC_F * kk2) * __frcp_rn(kk2);
            acc = fmaf(k2v.w * qg, fmaf(cr2, cr2, ci2 * ci2), acc);
            kx = k3.x * ax; ky = k3.y * ay; kz = k3.z * az;
            kk2 = kx * kx + ky * ky + kz * kz;
            qg = __expf(-K2FAC_F * kk2) * __frcp_rn(kk2);
            acc = fmaf(k3.w * qg, fmaf(cr3, cr3, ci3 * ci3), acc);
            sacc[warp] = acc;
        }
        __syncthreads();
        if (threadIdx.x == 0) {
            float tot = 0.0f;
#pragma unroll
            for (int w2 = 0; w2 < 8; w2++) tot += sacc[w2];
            g_recip_part[kblk * NUM_BATCH + b] = tot;   // overwrite, no atomic
        }
    }
}

// ------------------------------------------------------------------
// finalize: one block per batch, 512 threads. Warp 0 sums the KB recip
// partials; then elementwise combine. g_ereal is reset by its reader
// (race-free, restores the zero invariant for the next graph replay).
// ------------------------------------------------------------------
__global__ void k_final(const float* __restrict__ Qa,
                        const float* __restrict__ cell,
                        float* __restrict__ out) {
    int b = blockIdx.x;
    int a = threadIdx.x;            // 0..511
    int n = b * ATOMS_PER_BATCH + a;
    __shared__ float srec;

    float er = g_ereal[n];
    g_ereal[n] = 0.0f;              // restore invariant for next replay

    if (a < 32) {
        float t = 0.0f;
        for (int kb = a; kb < KB; kb += 32)
            t += g_recip_part[kb * NUM_BATCH + b];
#pragma unroll
        for (int o = 16; o > 0; o >>= 1) t += __shfl_down_sync(FULL, t, o);
        if (a == 0) srec = t;
    }
    __syncthreads();
    float rec = srec;

    float q = Qa[n];
    float q2 = q * q;
    float w = q2 + EPS_F;
    float wnorm = g_wnorm[b];

    float Lx = cell[b * 9 + 0];
    float Ly = cell[b * 9 + 4];
    float Lz = cell[b * 9 + 8];
    float erec = (w / wnorm) * (TWO_PI_F / (Lx * Ly * Lz)) * rec;
    out[n] = er + erec - ALPHA_F * ONE_OVER_SQRTPI_F * q2;
}

// ------------------------------------------------------------------
extern "C" void kernel_launch(void* const* d_in, const int* in_sizes, int n_in,
                              void* d_out, int out_size) {
    const float* Qa    = (const float*)d_in[0];
    const float* rij   = (const float*)d_in[1];
    const float* R     = (const float*)d_in[2];
    const float* cell  = (const float*)d_in[3];
    const int*   idx_i = (const int*)d_in[5];
    const int*   idx_j = (const int*)d_in[6];
    float* out = (float*)d_out;

    k_main<<<TOTAL_BLOCKS, 256>>>(Qa, rij, idx_i, idx_j, R, cell);
    k_final<<<NUM_BATCH, ATOMS_PER_BATCH>>>(Qa, cell, out);
}

// round 9
// speedup vs baseline: 2.0909x; 1.2343x over previous
#include <cuda_runtime.h>
#include <cuda_bf16.h>
#include <math.h>

// ---- static problem config (matches reference) ----
#define N_ATOMS 16384
#define NUM_BATCH 32
#define ATOMS_PER_BATCH 512
#define N_PAIRS 1048576

#define ALPHA_F       0.401f            // 4/10 + 0.001
#define K2FAC_F       1.5547167f        // 0.25 / ALPHA^2
#define TWO_PI_F      6.283185307179586f
#define ONE_OVER_SQRTPI_F 0.5641895835477563f
#define EPS_F         1e-8f
#define FULL 0xFFFFFFFFu

#define REAL_BLOCKS 256                 // 256 blocks * 8 warps * 512 pairs = 1M
#define PAIRS_PER_WARP 512
#define KMAXI 8
#define JGROUPS 8                       // recip blocks per batch

// ------------------------------------------------------------------
// Compile-time canonical half of the k lattice (KMAX=8 is static).
// canonical: mx>0 | (mx=0 & my>0) | (mx=0 & my=0 & mz>0); 0<|k|^2<=64.
// ------------------------------------------------------------------
struct alignas(16) KEntry { float x, y, z, w; };

constexpr int count_khalf() {
    int n = 0;
    for (int mx = -KMAXI; mx <= KMAXI; mx++)
        for (int my = -KMAXI; my <= KMAXI; my++)
            for (int mz = -KMAXI; mz <= KMAXI; mz++) {
                int k2 = mx * mx + my * my + mz * mz;
                if (k2 == 0 || k2 > KMAXI * KMAXI) continue;
                if ((mx > 0) || (mx == 0 && (my > 0 || (my == 0 && mz > 0)))) n++;
            }
    return n;
}
constexpr int NK   = count_khalf();
constexpr int KB   = (NK + 31) / 32;     // number of 32-k chunks
constexpr int KPAD = KB * 32;

struct KTable { KEntry e[KPAD]; };

constexpr KTable make_ktable() {
    KTable t{};
    int n = 0;
    for (int mx = -KMAXI; mx <= KMAXI; mx++)
        for (int my = -KMAXI; my <= KMAXI; my++)
            for (int mz = -KMAXI; mz <= KMAXI; mz++) {
                int k2 = mx * mx + my * my + mz * mz;
                if (k2 == 0 || k2 > KMAXI * KMAXI) continue;
                if (!((mx > 0) || (mx == 0 && (my > 0 || (my == 0 && mz > 0))))) continue;
                t.e[n].x = (float)mx; t.e[n].y = (float)my;
                t.e[n].z = (float)mz; t.e[n].w = 2.0f;    // +k and -k
                n++;
            }
    for (; n < KPAD; n++) { t.e[n].x = 1.0f; t.e[n].y = 0.0f; t.e[n].z = 0.0f; t.e[n].w = 0.0f; }
    return t;
}
constexpr KTable h_ktable = make_ktable();
__constant__ KTable c_kt = h_ktable;

#define WNORM_BLOCKS 32
#define RECIP_BASE   (REAL_BLOCKS + WNORM_BLOCKS)
#define RECIP_BLOCKS (NUM_BATCH * JGROUPS)
#define TOTAL_BLOCKS (RECIP_BASE + RECIP_BLOCKS)
#define NPART        (RECIP_BLOCKS * 8)  // one partial per (block, warp)

// scratch (no allocations). g_recip_part / g_wnorm are overwritten every
// call; g_ereal is reset by its reader in k_final so every graph replay
// starts from zero.
__device__ float g_recip_part[NPART];
__device__ float g_wnorm[NUM_BATCH];
__device__ float g_ereal[N_ATOMS];

// ------------------------------------------------------------------
// fused main:
//   blocks [0, 256)           real space (coalesced pairs, warp segscan)
//   blocks [256, 288)         per-batch wnorm (overwrite g_wnorm)
//   blocks [288, 288+256)     recip: block = (batch b, group j).
//     Stage 512 atoms as (theta_xyz, q) float4 in SMEM ONCE, then loop
//     k-chunks {j, j+8, ...}: 8 warps x 4 k per chunk, 4 sincos pairs
//     per staged LDS.128. lane0 accumulates across chunks; one plain
//     global store per warp at the end (no atomics).
// ------------------------------------------------------------------
__global__ void __launch_bounds__(256) k_main(
        const float* __restrict__ Qa,
        const float* __restrict__ rij,
        const int*   __restrict__ idx_i,
        const int*   __restrict__ idx_j,
        const float* __restrict__ R,
        const float* __restrict__ cell) {
    int bid = blockIdx.x;
    int warp = threadIdx.x >> 5;
    int lane = threadIdx.x & 31;

    if (bid < REAL_BLOCKS) {
        // ---------------- real space ----------------
        int gw = bid * 8 + warp;
        int base = gw * PAIRS_PER_WARP;
#pragma unroll 2
        for (int it = 0; it < PAIRS_PER_WARP / 32; it++) {
            int p = base + it * 32 + lane;          // coalesced
            int ii = idx_i[p];
            int jj = idx_j[p];
            float rr = rij[p];
            float fac = __ldg(&Qa[ii]) * __ldg(&Qa[jj]);

            // C-inf switch, fast path
            float x = (rr - 2.5f) * 0.2f;
            float f;
            if (x <= 0.0f)      f = 1.0f;
            else if (x >= 1.0f) f = 0.0f;
            else {
                float fp = __expf(-__frcp_rn(x));
                float fm = __expf(-__frcp_rn(1.0f - x));
                f = fm * __frcp_rn(fp + fm);
            }
            float damped = rsqrtf(fmaf(rr, rr, 1.0f));
            float coul = __frcp_rn(rr);

            // erfc via Abramowitz-Stegun 7.1.26 (abs err <= 1.5e-7)
            float xa = ALPHA_F * rr;
            float t = __frcp_rn(fmaf(0.3275911f, xa, 1.0f));
            float poly = t * fmaf(t, fmaf(t, fmaf(t, fmaf(t, 1.061405429f,
                                -1.453152027f), 1.421413741f),
                                -0.284496736f), 0.254829592f);
            float er = poly * __expf(-xa * xa);

            float pw = fac * (f * damped + (1.0f - f) * coul) * er;

            // warp segmented reduction over sorted ii
            int prev = __shfl_up_sync(FULL, ii, 1);
            bool head = (lane == 0) || (ii != prev);
            unsigned hm = __ballot_sync(FULL, head);
            unsigned below = hm & (0xFFFFFFFFu >> (31 - lane));
            int hp = 31 - __clz(below);
            float s = pw;
#pragma unroll
            for (int d = 1; d < 32; d <<= 1) {
                float v = __shfl_up_sync(FULL, s, d);
                if (lane >= hp + d) s += v;
            }
            bool lastv = (lane == 31) || ((hm >> (lane + 1)) & 1u);
            if (lastv) atomicAdd(&g_ereal[ii], s);
        }
    } else if (bid < RECIP_BASE) {
        // ---------------- per-batch wnorm (overwrite) ----------------
        int b = bid - REAL_BLOCKS;
        __shared__ float sw[8];
        float acc = 0.0f;
        for (int a = threadIdx.x; a < ATOMS_PER_BATCH; a += 256) {
            float q = Qa[b * ATOMS_PER_BATCH + a];
            acc = fmaf(q, q, acc + EPS_F);
        }
#pragma unroll
        for (int o = 16; o > 0; o >>= 1) acc += __shfl_down_sync(FULL, acc, o);
        if (lane == 0) sw[warp] = acc;
        __syncthreads();
        if (threadIdx.x == 0) {
            float tot = 0.0f;
#pragma unroll
            for (int w2 = 0; w2 < 8; w2++) tot += sw[w2];
            g_wnorm[b] = tot;
        }
    } else {
        // ---------------- reciprocal space ----------------
        int idx = bid - RECIP_BASE;
        int b = idx & (NUM_BATCH - 1);          // batch
        int j = idx >> 5;                       // chunk group 0..7

        __shared__ float4 s4[ATOMS_PER_BATCH];  // (theta_x, theta_y, theta_z, q)

        float ax = TWO_PI_F * __frcp_rn(cell[b * 9 + 0]);
        float ay = TWO_PI_F * __frcp_rn(cell[b * 9 + 4]);
        float az = TWO_PI_F * __frcp_rn(cell[b * 9 + 8]);

        for (int a = threadIdx.x; a < ATOMS_PER_BATCH; a += 256) {
            int n = b * ATOMS_PER_BATCH + a;
            float4 v;
            v.x = R[n * 3 + 0] * ax;
            v.y = R[n * 3 + 1] * ay;
            v.z = R[n * 3 + 2] * az;
            v.w = Qa[n];
            s4[a] = v;
        }
        __syncthreads();

        const float4* kt = reinterpret_cast<const float4*>(c_kt.e);
        float blockAcc = 0.0f;                  // lane0 accumulator across chunks

        for (int chunk = j; chunk < KB; chunk += JGROUPS) {
            int kk = chunk * 32 + warp * 4;     // 4 k-vectors per warp
            float4 k0 = kt[kk + 0];
            float4 k1 = kt[kk + 1];
            float4 k2v = kt[kk + 2];
            float4 k3 = kt[kk + 3];

            float cr0 = 0.f, ci0 = 0.f, cr1 = 0.f, ci1 = 0.f;
            float cr2 = 0.f, ci2 = 0.f, cr3 = 0.f, ci3 = 0.f;

#pragma unroll 4
            for (int a = lane; a < ATOMS_PER_BATCH; a += 32) {
                float4 v = s4[a];
                float q = v.w;
                float d0 = fmaf(k0.x, v.x, fmaf(k0.y, v.y, k0.z * v.z));
                float d1 = fmaf(k1.x, v.x, fmaf(k1.y, v.y, k1.z * v.z));
                float d2 = fmaf(k2v.x, v.x, fmaf(k2v.y, v.y, k2v.z * v.z));
                float d3 = fmaf(k3.x, v.x, fmaf(k3.y, v.y, k3.z * v.z));
                float s0, c0, s1, c1, s2, c2, s3, c3;
                __sincosf(d0, &s0, &c0);
                __sincosf(d1, &s1, &c1);
                __sincosf(d2, &s2, &c2);
                __sincosf(d3, &s3, &c3);
                cr0 = fmaf(q, c0, cr0); ci0 = fmaf(q, s0, ci0);
                cr1 = fmaf(q, c1, cr1); ci1 = fmaf(q, s1, ci1);
                cr2 = fmaf(q, c2, cr2); ci2 = fmaf(q, s2, ci2);
                cr3 = fmaf(q, c3, cr3); ci3 = fmaf(q, s3, ci3);
            }
#pragma unroll
            for (int o = 16; o > 0; o >>= 1) {
                cr0 += __shfl_down_sync(FULL, cr0, o);
                ci0 += __shfl_down_sync(FULL, ci0, o);
                cr1 += __shfl_down_sync(FULL, cr1, o);
                ci1 += __shfl_down_sync(FULL, ci1, o);
                cr2 += __shfl_down_sync(FULL, cr2, o);
                ci2 += __shfl_down_sync(FULL, ci2, o);
                cr3 += __shfl_down_sync(FULL, cr3, o);
                ci3 += __shfl_down_sync(FULL, ci3, o);
            }
            if (lane == 0) {
                float kx, ky, kz, kk2, qg;
                kx = k0.x * ax; ky = k0.y * ay; kz = k0.z * az;
                kk2 = kx * kx + ky * ky + kz * kz;
                qg = __expf(-K2FAC_F * kk2) * __frcp_rn(kk2);
                blockAcc = fmaf(k0.w * qg, fmaf(cr0, cr0, ci0 * ci0), blockAcc);
                kx = k1.x * ax; ky = k1.y * ay; kz = k1.z * az;
                kk2 = kx * kx + ky * ky + kz * kz;
                qg = __expf(-K2FAC_F * kk2) * __frcp_rn(kk2);
                blockAcc = fmaf(k1.w * qg, fmaf(cr1, cr1, ci1 * ci1), blockAcc);
                kx = k2v.x * ax; ky = k2v.y * ay; kz = k2v.z * az;
                kk2 = kx * kx + ky * ky + kz * kz;
                qg = __expf(-K2FAC_F * kk2) * __frcp_rn(kk2);
                blockAcc = fmaf(k2v.w * qg, fmaf(cr2, cr2, ci2 * ci2), blockAcc);
                kx = k3.x * ax; ky = k3.y * ay; kz = k3.z * az;
                kk2 = kx * kx + ky * ky + kz * kz;
                qg = __expf(-K2FAC_F * kk2) * __frcp_rn(kk2);
                blockAcc = fmaf(k3.w * qg, fmaf(cr3, cr3, ci3 * ci3), blockAcc);
            }
        }
        if (lane == 0) {
            // partial index: (j*8 + warp)*NUM_BATCH + b   -> plain store
            g_recip_part[(j * 8 + warp) * NUM_BATCH + b] = blockAcc;
        }
    }
}

// ------------------------------------------------------------------
// finalize: 128 blocks x 128 threads (4 blocks per batch). Warp 0 of
// each block sums the 64 recip partials of its batch; elementwise
// combine. g_ereal reset by its reader (zero invariant for replays).
// ------------------------------------------------------------------
__global__ void k_final(const float* __restrict__ Qa,
                        const float* __restrict__ cell,
                        float* __restrict__ out) {
    int n = blockIdx.x * 128 + threadIdx.x;
    int b = n >> 9;                 // same for whole block (128 | 512)
    int a = threadIdx.x;
    __shared__ float srec;

    float er = g_ereal[n];
    g_ereal[n] = 0.0f;              // restore invariant for next replay

    if (a < 32) {
        float t = 0.0f;
#pragma unroll
        for (int m = 0; m < 2; m++)     // 64 partials per batch
            t += g_recip_part[(a + m * 32) * NUM_BATCH + b];
#pragma unroll
        for (int o = 16; o > 0; o >>= 1) t += __shfl_down_sync(FULL, t, o);
        if (a == 0) srec = t;
    }
    __syncthreads();
    float rec = srec;

    float q = Qa[n];
    float q2 = q * q;
    float w = q2 + EPS_F;
    float wnorm = g_wnorm[b];

    float Lx = cell[b * 9 + 0];
    float Ly = cell[b * 9 + 4];
    float Lz = cell[b * 9 + 8];
    float erec = (w / wnorm) * (TWO_PI_F / (Lx * Ly * Lz)) * rec;
    out[n] = er + erec - ALPHA_F * ONE_OVER_SQRTPI_F * q2;
}

// ------------------------------------------------------------------
extern "C" void kernel_launch(void* const* d_in, const int* in_sizes, int n_in,
                              void* d_out, int out_size) {
    const float* Qa    = (const float*)d_in[0];
    const float* rij   = (const float*)d_in[1];
    const float* R     = (const float*)d_in[2];
    const float* cell  = (const float*)d_in[3];
    const int*   idx_i = (const int*)d_in[5];
    const int*   idx_j = (const int*)d_in[6];
    float* out = (float*)d_out;

    k_main<<<TOTAL_BLOCKS, 256>>>(Qa, rij, idx_i, idx_j, R, cell);
    k_final<<<N_ATOMS / 128, 128>>>(Qa, cell, out);
}